// round 1
// baseline (speedup 1.0000x reference)
#include <cuda_runtime.h>
#include <math.h>

#define Bsz   4
#define NTOK  1280
#define NM    256
#define NS    1024
#define DIMC  768
#define HEADS 12
#define HD    64
#define MEMN  1280
#define LFULL 2560
#define KSEL_M 128
#define KSEL_S 640

// ---------------- scratch (device globals; no allocation) ----------------
__device__ float g_low[Bsz*NTOK*24];            // qkv lora low [m][g*8+r]
__device__ float g_q[Bsz*HEADS*NTOK*HD];        // pre-scaled by D^-0.5
__device__ float g_k[Bsz*HEADS*NTOK*HD];
__device__ float g_v[Bsz*HEADS*NTOK*HD];
__device__ float g_idlowk[Bsz*NM*8];
__device__ float g_idlowv[Bsz*NM*8];
__device__ float g_IDK[Bsz*NM*HEADS];
__device__ float g_IDV[Bsz*NM*DIMC];
__device__ float g_xo[Bsz*NTOK*DIMC];
__device__ float g_coef[Bsz*NTOK*32];           // 0.125*route_e*plow[e,r]

static __device__ __forceinline__ unsigned f2u(float f) {
    unsigned u = __float_as_uint(f);
    return (u & 0x80000000u) ? ~u : (u | 0x80000000u);
}

// ---------------- small dot kernels ----------------
__global__ __launch_bounds__(256) void low_qkv_kernel(const float* __restrict__ X,
                                                      const float* __restrict__ qkvA) {
    int row = blockIdx.x;                       // 0..5119
    __shared__ float xs[DIMC];
    for (int i = threadIdx.x; i < DIMC; i += 256) xs[i] = X[(size_t)row*DIMC + i];
    __syncthreads();
    int wid = threadIdx.x >> 5, lane = threadIdx.x & 31;
    for (int o = wid; o < 24; o += 8) {
        const float* a = qkvA + (size_t)o*DIMC;
        float s = 0.f;
        for (int c = lane; c < DIMC; c += 32) s += xs[c]*a[c];
        for (int off = 16; off; off >>= 1) s += __shfl_down_sync(0xffffffffu, s, off);
        if (lane == 0) g_low[row*24 + o] = s;
    }
}

__global__ __launch_bounds__(256) void id_lows_kernel(const float* __restrict__ IDT,
                                                      const float* __restrict__ idkA,
                                                      const float* __restrict__ idvA) {
    int row = blockIdx.x;                       // 0..1023
    __shared__ float xs[DIMC];
    for (int i = threadIdx.x; i < DIMC; i += 256) xs[i] = IDT[(size_t)row*DIMC + i];
    __syncthreads();
    int wid = threadIdx.x >> 5, lane = threadIdx.x & 31;
    for (int o = wid; o < 16; o += 8) {
        const float* a = (o < 8) ? (idkA + (size_t)o*DIMC) : (idvA + (size_t)(o-8)*DIMC);
        float s = 0.f;
        for (int c = lane; c < DIMC; c += 32) s += xs[c]*a[c];
        for (int off = 16; off; off >>= 1) s += __shfl_down_sync(0xffffffffu, s, off);
        if (lane == 0) {
            if (o < 8) g_idlowk[row*8 + o] = s;
            else       g_idlowv[row*8 + (o-8)] = s;
        }
    }
}

__global__ __launch_bounds__(256) void idk_kernel(const float* __restrict__ IDT,
                                                  const float* __restrict__ Widk,
                                                  const float* __restrict__ bidk,
                                                  const float* __restrict__ idkB) {
    int row = blockIdx.x;                       // 0..1023
    __shared__ float xs[DIMC];
    for (int i = threadIdx.x; i < DIMC; i += 256) xs[i] = IDT[(size_t)row*DIMC + i];
    __syncthreads();
    int wid = threadIdx.x >> 5, lane = threadIdx.x & 31;
    for (int o = wid; o < HEADS; o += 8) {
        const float* a = Widk + (size_t)o*DIMC;
        float s = 0.f;
        for (int c = lane; c < DIMC; c += 32) s += xs[c]*a[c];
        for (int off = 16; off; off >>= 1) s += __shfl_down_sync(0xffffffffu, s, off);
        if (lane == 0) {
            float l = 0.f;
            #pragma unroll
            for (int r = 0; r < 8; r++) l += g_idlowk[row*8 + r] * idkB[o*8 + r];
            g_IDK[row*HEADS + o] = s + bidk[o] + 0.125f*l;
        }
    }
}

__global__ __launch_bounds__(256) void coef_kernel(const float* __restrict__ routeW,
                                                   const float* __restrict__ projA) {
    int row = blockIdx.x;                       // 0..5119
    __shared__ float xs[DIMC];
    __shared__ float dots[36];
    __shared__ float routeS[4];
    for (int i = threadIdx.x; i < DIMC; i += 256) xs[i] = g_xo[(size_t)row*DIMC + i];
    __syncthreads();
    int wid = threadIdx.x >> 5, lane = threadIdx.x & 31;
    for (int o = wid; o < 36; o += 8) {
        const float* a = (o < 4) ? (routeW + (size_t)o*DIMC) : (projA + (size_t)(o-4)*DIMC);
        float s = 0.f;
        for (int c = lane; c < DIMC; c += 32) s += xs[c]*a[c];
        for (int off = 16; off; off >>= 1) s += __shfl_down_sync(0xffffffffu, s, off);
        if (lane == 0) dots[o] = s;
    }
    __syncthreads();
    if (threadIdx.x == 0) {
        float m = fmaxf(fmaxf(dots[0], dots[1]), fmaxf(dots[2], dots[3]));
        float e[4]; float s0 = 0.f;
        for (int i = 0; i < 4; i++) { e[i] = expf(dots[i]-m); s0 += e[i]; }
        for (int i = 0; i < 4; i++) routeS[i] = e[i]/s0;
    }
    __syncthreads();
    if (threadIdx.x < 32) {
        int t = threadIdx.x;
        g_coef[row*32 + t] = 0.125f * routeS[t >> 3] * dots[4 + t];
    }
}

// ---------------- GEMMs: 64x64x16 tiles, 4x4 microtile ----------------
__global__ __launch_bounds__(256) void gemm_qkv_kernel(const float* __restrict__ X,
                                                       const float* __restrict__ W,
                                                       const float* __restrict__ bias,
                                                       const float* __restrict__ qkvB) {
    __shared__ __align__(16) float As[16*68];
    __shared__ __align__(16) float Bs[16*68];
    int tid = threadIdx.x;
    int tx = tid & 15, ty = tid >> 4;
    int m0 = blockIdx.y * 64, n0 = blockIdx.x * 64;
    int lr = tid >> 2, lc = (tid & 3) * 4;
    float acc[4][4];
    #pragma unroll
    for (int i = 0; i < 4; i++)
        #pragma unroll
        for (int j = 0; j < 4; j++) acc[i][j] = 0.f;
    for (int k0 = 0; k0 < DIMC; k0 += 16) {
        float4 a4 = *(const float4*)(X + (size_t)(m0+lr)*DIMC + k0 + lc);
        float4 b4 = *(const float4*)(W + (size_t)(n0+lr)*DIMC + k0 + lc);
        As[(lc+0)*68+lr]=a4.x; As[(lc+1)*68+lr]=a4.y; As[(lc+2)*68+lr]=a4.z; As[(lc+3)*68+lr]=a4.w;
        Bs[(lc+0)*68+lr]=b4.x; Bs[(lc+1)*68+lr]=b4.y; Bs[(lc+2)*68+lr]=b4.z; Bs[(lc+3)*68+lr]=b4.w;
        __syncthreads();
        #pragma unroll
        for (int kk = 0; kk < 16; kk++) {
            float4 a = *(const float4*)&As[kk*68 + ty*4];
            float4 b = *(const float4*)&Bs[kk*68 + tx*4];
            float av[4] = {a.x,a.y,a.z,a.w}, bv[4] = {b.x,b.y,b.z,b.w};
            #pragma unroll
            for (int i = 0; i < 4; i++)
                #pragma unroll
                for (int j = 0; j < 4; j++) acc[i][j] += av[i]*bv[j];
        }
        __syncthreads();
    }
    #pragma unroll
    for (int i = 0; i < 4; i++) {
        int m = m0 + ty*4 + i;
        int bb = m / NTOK, nn = m % NTOK;
        const float* lowr = g_low + m*24;
        #pragma unroll
        for (int j = 0; j < 4; j++) {
            int n = n0 + tx*4 + j;
            int g = n / DIMC, c = n % DIMC;
            float v = acc[i][j] + bias[n];
            float l = 0.f;
            #pragma unroll
            for (int r = 0; r < 8; r++) l += lowr[g*8+r] * qkvB[((size_t)g*DIMC + c)*8 + r];
            v += 0.125f * l;
            int h = c >> 6, d = c & 63;
            size_t idx = (((size_t)bb*HEADS + h)*NTOK + nn)*HD + d;
            if (g == 0)      g_q[idx] = v * 0.125f;   // * D^-0.5
            else if (g == 1) g_k[idx] = v;
            else             g_v[idx] = v;
        }
    }
}

__global__ __launch_bounds__(256) void gemm_idv_kernel(const float* __restrict__ X,
                                                       const float* __restrict__ W,
                                                       const float* __restrict__ bias,
                                                       const float* __restrict__ idvB) {
    __shared__ __align__(16) float As[16*68];
    __shared__ __align__(16) float Bs[16*68];
    int tid = threadIdx.x;
    int tx = tid & 15, ty = tid >> 4;
    int m0 = blockIdx.y * 64, n0 = blockIdx.x * 64;
    int lr = tid >> 2, lc = (tid & 3) * 4;
    float acc[4][4];
    #pragma unroll
    for (int i = 0; i < 4; i++)
        #pragma unroll
        for (int j = 0; j < 4; j++) acc[i][j] = 0.f;
    for (int k0 = 0; k0 < DIMC; k0 += 16) {
        float4 a4 = *(const float4*)(X + (size_t)(m0+lr)*DIMC + k0 + lc);
        float4 b4 = *(const float4*)(W + (size_t)(n0+lr)*DIMC + k0 + lc);
        As[(lc+0)*68+lr]=a4.x; As[(lc+1)*68+lr]=a4.y; As[(lc+2)*68+lr]=a4.z; As[(lc+3)*68+lr]=a4.w;
        Bs[(lc+0)*68+lr]=b4.x; Bs[(lc+1)*68+lr]=b4.y; Bs[(lc+2)*68+lr]=b4.z; Bs[(lc+3)*68+lr]=b4.w;
        __syncthreads();
        #pragma unroll
        for (int kk = 0; kk < 16; kk++) {
            float4 a = *(const float4*)&As[kk*68 + ty*4];
            float4 b = *(const float4*)&Bs[kk*68 + tx*4];
            float av[4] = {a.x,a.y,a.z,a.w}, bv[4] = {b.x,b.y,b.z,b.w};
            #pragma unroll
            for (int i = 0; i < 4; i++)
                #pragma unroll
                for (int j = 0; j < 4; j++) acc[i][j] += av[i]*bv[j];
        }
        __syncthreads();
    }
    #pragma unroll
    for (int i = 0; i < 4; i++) {
        int m = m0 + ty*4 + i;
        #pragma unroll
        for (int j = 0; j < 4; j++) {
            int c = n0 + tx*4 + j;
            float v = acc[i][j] + bias[c];
            float l = 0.f;
            #pragma unroll
            for (int r = 0; r < 8; r++) l += g_idlowv[m*8+r] * idvB[(size_t)c*8 + r];
            g_IDV[(size_t)m*DIMC + c] = v + 0.125f*l;
        }
    }
}

__global__ __launch_bounds__(256) void gemm_out_kernel(const float* __restrict__ W,
                                                       const float* __restrict__ bias,
                                                       const float* __restrict__ projB,
                                                       float* __restrict__ OUT) {
    __shared__ __align__(16) float As[16*68];
    __shared__ __align__(16) float Bs[16*68];
    int tid = threadIdx.x;
    int tx = tid & 15, ty = tid >> 4;
    int m0 = blockIdx.y * 64, n0 = blockIdx.x * 64;
    int lr = tid >> 2, lc = (tid & 3) * 4;
    float acc[4][4];
    #pragma unroll
    for (int i = 0; i < 4; i++)
        #pragma unroll
        for (int j = 0; j < 4; j++) acc[i][j] = 0.f;
    for (int k0 = 0; k0 < DIMC; k0 += 16) {
        float4 a4 = *(const float4*)(g_xo + (size_t)(m0+lr)*DIMC + k0 + lc);
        float4 b4 = *(const float4*)(W + (size_t)(n0+lr)*DIMC + k0 + lc);
        As[(lc+0)*68+lr]=a4.x; As[(lc+1)*68+lr]=a4.y; As[(lc+2)*68+lr]=a4.z; As[(lc+3)*68+lr]=a4.w;
        Bs[(lc+0)*68+lr]=b4.x; Bs[(lc+1)*68+lr]=b4.y; Bs[(lc+2)*68+lr]=b4.z; Bs[(lc+3)*68+lr]=b4.w;
        __syncthreads();
        #pragma unroll
        for (int kk = 0; kk < 16; kk++) {
            float4 a = *(const float4*)&As[kk*68 + ty*4];
            float4 b = *(const float4*)&Bs[kk*68 + tx*4];
            float av[4] = {a.x,a.y,a.z,a.w}, bv[4] = {b.x,b.y,b.z,b.w};
            #pragma unroll
            for (int i = 0; i < 4; i++)
                #pragma unroll
                for (int j = 0; j < 4; j++) acc[i][j] += av[i]*bv[j];
        }
        __syncthreads();
    }
    #pragma unroll
    for (int i = 0; i < 4; i++) {
        int m = m0 + ty*4 + i;
        const float* cf = g_coef + m*32;
        #pragma unroll
        for (int j = 0; j < 4; j++) {
            int c = n0 + tx*4 + j;
            float v = acc[i][j] + bias[c];
            float l = 0.f;
            #pragma unroll
            for (int er = 0; er < 32; er++) {
                int e = er >> 3, r = er & 7;
                l += cf[er] * projB[((size_t)e*DIMC + c)*8 + r];
            }
            OUT[(size_t)m*DIMC + c] = v + l;
        }
    }
}

// ---------------- elementwise k_m_id / v_m_id ----------------
__global__ __launch_bounds__(256) void ew_kernel(float* __restrict__ kmid,
                                                 float* __restrict__ vmid) {
    int idx = blockIdx.x*256 + threadIdx.x;     // < 786432
    int d = idx & 63;
    int m = (idx >> 6) & 255;
    int h = (idx >> 14) % HEADS;
    int b = (idx >> 14) / HEADS;
    size_t src = (((size_t)b*HEADS + h)*NTOK + m)*HD + d;
    float idk = g_IDK[(b*NM + m)*HEADS + h];
    kmid[idx] = g_k[src] * (1.f + tanhf(idk));
    vmid[idx] = g_v[src] + g_IDV[((size_t)b*NM + m)*DIMC + h*HD + d];
}

// ---------------- attn over memory tokens (256 keys, top-128) ----------------
__global__ __launch_bounds__(256) void attn_m_kernel(const float* __restrict__ KM,
                                                     const float* __restrict__ VM) {
    int bid = blockIdx.x;
    int qm = bid & 255, bh = bid >> 8;
    int b = bh / HEADS, h = bh % HEADS;
    __shared__ float qrow[HD];
    __shared__ float sc[NM];
    __shared__ int s_cnt;
    __shared__ int s_wc[8];
    __shared__ float s_red[8];
    __shared__ float s_part[4][HD];
    int tid = threadIdx.x, lane = tid & 31, wid = tid >> 5;
    if (tid < HD) qrow[tid] = g_q[((size_t)bh*NTOK + qm)*HD + tid];
    __syncthreads();
    const float* kr = KM + ((size_t)bh*NM + tid)*HD;
    float s = 0.f;
    #pragma unroll
    for (int d = 0; d < HD; d += 4) {
        float4 k4 = *(const float4*)(kr + d);
        s += qrow[d]*k4.x + qrow[d+1]*k4.y + qrow[d+2]*k4.z + qrow[d+3]*k4.w;
    }
    sc[tid] = s;
    unsigned u = f2u(s);
    unsigned T = 0u;
    for (int bit = 31; bit >= 0; bit--) {
        unsigned cand = T | (1u << bit);
        __syncthreads();
        if (tid == 0) s_cnt = 0;
        __syncthreads();
        unsigned bal = __ballot_sync(0xffffffffu, u >= cand);
        if (lane == 0) atomicAdd(&s_cnt, __popc(bal));
        __syncthreads();
        if (s_cnt >= KSEL_M) T = cand;
    }
    __syncthreads();
    if (tid == 0) s_cnt = 0;
    __syncthreads();
    unsigned balgt = __ballot_sync(0xffffffffu, u > T);
    if (lane == 0) atomicAdd(&s_cnt, __popc(balgt));
    __syncthreads();
    int need = KSEL_M - s_cnt;
    unsigned baleq = __ballot_sync(0xffffffffu, u == T);
    if (lane == 0) s_wc[wid] = __popc(baleq);
    __syncthreads();
    int off = 0;
    for (int w = 0; w < wid; w++) off += s_wc[w];
    int rank = off + __popc(baleq & ((1u << lane) - 1u));
    bool sel = (u > T) || ((u == T) && rank < need);
    // global max (= top value)
    float mx = s;
    for (int o = 16; o; o >>= 1) mx = fmaxf(mx, __shfl_xor_sync(0xffffffffu, mx, o));
    if (lane == 0) s_red[wid] = mx;
    __syncthreads();
    if (tid == 0) { float m2 = s_red[0]; for (int w = 1; w < 8; w++) m2 = fmaxf(m2, s_red[w]); s_red[0] = m2; }
    __syncthreads();
    float smax = s_red[0];
    __syncthreads();
    float e = sel ? expf(s - smax) : 0.f;
    float ss = e;
    for (int o = 16; o; o >>= 1) ss += __shfl_xor_sync(0xffffffffu, ss, o);
    if (lane == 0) s_red[wid] = ss;
    __syncthreads();
    if (tid == 0) { float t2 = 0.f; for (int w = 0; w < 8; w++) t2 += s_red[w]; s_red[0] = t2; }
    __syncthreads();
    float inv = 1.f / s_red[0];
    sc[tid] = e * inv;
    __syncthreads();
    int d = tid & 63, grp = tid >> 6;
    float acc = 0.f;
    for (int j = grp; j < NM; j += 4) {
        float w = sc[j];
        if (w != 0.f) acc += w * VM[((size_t)bh*NM + j)*HD + d];
    }
    s_part[grp][d] = acc;
    __syncthreads();
    if (tid < HD) {
        float o4 = s_part[0][tid] + s_part[1][tid] + s_part[2][tid] + s_part[3][tid];
        g_xo[((size_t)b*NTOK + qm)*DIMC + h*HD + tid] = o4;
    }
}

// ---------------- attn over full sequence (2560 keys, top-640) ----------------
__global__ __launch_bounds__(256) void attn_s_kernel(const float* __restrict__ memK,
                                                     const float* __restrict__ memV,
                                                     const float* __restrict__ VMID) {
    int bid = blockIdx.x;
    int qs = bid & 1023, bh = bid >> 10;
    int b = bh / HEADS, h = bh % HEADS;
    __shared__ float qrow[HD];
    __shared__ float sc[LFULL];
    __shared__ int s_cnt;
    __shared__ int s_wc[8];
    __shared__ float s_red[8];
    __shared__ float s_part[4][HD];
    int tid = threadIdx.x, lane = tid & 31, wid = tid >> 5;
    if (tid < HD) qrow[tid] = g_q[((size_t)bh*NTOK + NM + qs)*HD + tid];
    __syncthreads();
    const float* kmemb = memK + (size_t)bh*MEMN*HD;
    const float* kbufb = g_k + (size_t)bh*NTOK*HD;
    float sv[10]; unsigned uk[10];
    #pragma unroll
    for (int i = 0; i < 10; i++) {
        int j = i*256 + tid;
        const float* kr = (j < MEMN) ? (kmemb + (size_t)j*HD) : (kbufb + (size_t)(j-MEMN)*HD);
        float s = 0.f;
        #pragma unroll
        for (int d = 0; d < HD; d += 4) {
            float4 k4 = *(const float4*)(kr + d);
            s += qrow[d]*k4.x + qrow[d+1]*k4.y + qrow[d+2]*k4.z + qrow[d+3]*k4.w;
        }
        sv[i] = s; sc[j] = s; uk[i] = f2u(s);
    }
    unsigned T = 0u;
    for (int bit = 31; bit >= 0; bit--) {
        unsigned cand = T | (1u << bit);
        __syncthreads();
        if (tid == 0) s_cnt = 0;
        __syncthreads();
        int c = 0;
        #pragma unroll
        for (int i = 0; i < 10; i++) c += (uk[i] >= cand);
        for (int o = 16; o; o >>= 1) c += __shfl_down_sync(0xffffffffu, c, o);
        if (lane == 0) atomicAdd(&s_cnt, c);
        __syncthreads();
        if (s_cnt >= KSEL_S) T = cand;
    }
    __syncthreads();
    if (tid == 0) s_cnt = 0;
    __syncthreads();
    {
        int c = 0;
        #pragma unroll
        for (int i = 0; i < 10; i++) c += (uk[i] > T);
        for (int o = 16; o; o >>= 1) c += __shfl_down_sync(0xffffffffu, c, o);
        if (lane == 0) atomicAdd(&s_cnt, c);
    }
    __syncthreads();
    int need = KSEL_S - s_cnt;
    bool sel[10];
    int base = 0;
    for (int i = 0; i < 10; i++) {
        bool eq = (uk[i] == T);
        unsigned bal = __ballot_sync(0xffffffffu, eq);
        __syncthreads();
        if (lane == 0) s_wc[wid] = __popc(bal);
        __syncthreads();
        int offw = 0, tot = 0;
        for (int w = 0; w < 8; w++) { int cc = s_wc[w]; tot += cc; if (w < wid) offw += cc; }
        int rank = base + offw + __popc(bal & ((1u << lane) - 1u));
        sel[i] = (uk[i] > T) || (eq && rank < need);
        base += tot;
    }
    float mx = sv[0];
    #pragma unroll
    for (int i = 1; i < 10; i++) mx = fmaxf(mx, sv[i]);
    for (int o = 16; o; o >>= 1) mx = fmaxf(mx, __shfl_xor_sync(0xffffffffu, mx, o));
    __syncthreads();
    if (lane == 0) s_red[wid] = mx;
    __syncthreads();
    if (tid == 0) { float m2 = s_red[0]; for (int w = 1; w < 8; w++) m2 = fmaxf(m2, s_red[w]); s_red[0] = m2; }
    __syncthreads();
    float smax = s_red[0];
    float esum = 0.f; float ev[10];
    #pragma unroll
    for (int i = 0; i < 10; i++) { ev[i] = sel[i] ? expf(sv[i]-smax) : 0.f; esum += ev[i]; }
    for (int o = 16; o; o >>= 1) esum += __shfl_xor_sync(0xffffffffu, esum, o);
    __syncthreads();
    if (lane == 0) s_red[wid] = esum;
    __syncthreads();
    if (tid == 0) { float t2 = 0.f; for (int w = 0; w < 8; w++) t2 += s_red[w]; s_red[0] = t2; }
    __syncthreads();
    float inv = 1.f / s_red[0];
    #pragma unroll
    for (int i = 0; i < 10; i++) sc[i*256 + tid] = ev[i]*inv;
    __syncthreads();
    int d = tid & 63, grp = tid >> 6;
    const float* vmemb = memV + (size_t)bh*MEMN*HD;
    const float* vbufb = g_v + (size_t)bh*NTOK*HD;
    const float* vmidb = VMID + (size_t)bh*NM*HD;
    float acc = 0.f;
    for (int j = grp; j < LFULL; j += 4) {
        float w = sc[j];
        if (w != 0.f) {
            const float* vr;
            if (j < MEMN) vr = vmemb + (size_t)j*HD;
            else if (j < MEMN + NM) vr = vmidb + (size_t)(j-MEMN)*HD;
            else vr = vbufb + (size_t)(j-MEMN)*HD;
            acc += w * vr[d];
        }
    }
    s_part[grp][d] = acc;
    __syncthreads();
    if (tid < HD) {
        float o4 = s_part[0][tid] + s_part[1][tid] + s_part[2][tid] + s_part[3][tid];
        g_xo[((size_t)b*NTOK + NM + qs)*DIMC + h*HD + tid] = o4;
    }
}

// ---------------- launch ----------------
extern "C" void kernel_launch(void* const* d_in, const int* in_sizes, int n_in,
                              void* d_out, int out_size) {
    const float* x        = (const float*)d_in[0];
    const float* id_total = (const float*)d_in[1];
    const float* mem_k    = (const float*)d_in[2];
    const float* mem_v    = (const float*)d_in[3];
    const float* W_qkv    = (const float*)d_in[4];
    const float* b_qkv    = (const float*)d_in[5];
    const float* qkv_A    = (const float*)d_in[6];
    const float* qkv_B    = (const float*)d_in[7];
    const float* W_proj   = (const float*)d_in[8];
    const float* b_proj   = (const float*)d_in[9];
    const float* route_W  = (const float*)d_in[10];
    const float* proj_A   = (const float*)d_in[11];
    const float* proj_B   = (const float*)d_in[12];
    const float* W_idk    = (const float*)d_in[13];
    const float* b_idk    = (const float*)d_in[14];
    const float* idk_A    = (const float*)d_in[15];
    const float* idk_B    = (const float*)d_in[16];
    const float* W_idv    = (const float*)d_in[17];
    const float* b_idv    = (const float*)d_in[18];
    const float* idv_A    = (const float*)d_in[19];
    const float* idv_B    = (const float*)d_in[20];
    (void)in_sizes; (void)n_in; (void)out_size;

    float* out  = (float*)d_out;
    float* kmid = out + (size_t)Bsz*NTOK*DIMC;
    float* vmid = kmid + (size_t)Bsz*HEADS*NM*HD;

    low_qkv_kernel<<<Bsz*NTOK, 256>>>(x, qkv_A);
    id_lows_kernel<<<Bsz*NM, 256>>>(id_total, idk_A, idv_A);
    gemm_qkv_kernel<<<dim3(36, 80), 256>>>(x, W_qkv, b_qkv, qkv_B);
    gemm_idv_kernel<<<dim3(12, 16), 256>>>(id_total, W_idv, b_idv, idv_B);
    idk_kernel<<<Bsz*NM, 256>>>(id_total, W_idk, b_idk, idk_B);
    ew_kernel<<<(Bsz*HEADS*NM*HD)/256, 256>>>(kmid, vmid);
    attn_m_kernel<<<Bsz*HEADS*NM, 256>>>(kmid, vmid);
    attn_s_kernel<<<Bsz*HEADS*NS, 256>>>(mem_k, mem_v, vmid);
    coef_kernel<<<Bsz*NTOK, 256>>>(route_W, proj_A);
    gemm_out_kernel<<<dim3(12, 80), 256>>>(W_proj, b_proj, proj_B, out);
}

// round 2
// speedup vs baseline: 2.7636x; 2.7636x over previous
#include <cuda_runtime.h>
#include <math.h>

#define Bsz   4
#define NTOK  1280
#define NM    256
#define NS    1024
#define DIMC  768
#define HEADS 12
#define HD    64
#define MEMN  1280
#define LFULL 2560
#define KSEL_M 128
#define KSEL_S 640
#define BH    (Bsz*HEADS)
#define CH    12            // bh per score chunk

// ---------------- scratch (device globals; no allocation) ----------------
__device__ float g_low[Bsz*NTOK*24];
__device__ float g_q[BH*NTOK*HD];               // pre-scaled by D^-0.5
__device__ float g_k[BH*NTOK*HD];
__device__ float g_v[BH*NTOK*HD];
__device__ float g_idlowk[Bsz*NM*8];
__device__ float g_idlowv[Bsz*NM*8];
__device__ float g_IDK[Bsz*NM*HEADS];
__device__ float g_IDV[Bsz*NM*DIMC];
__device__ float g_xo[Bsz*NTOK*DIMC];
__device__ float g_coef[Bsz*NTOK*32];
__device__ float g_kf[BH*LFULL*HD];             // concat K (47MB)
__device__ float g_vf[BH*LFULL*HD];             // concat V (47MB)
__device__ float g_Ss[CH*NS*LFULL];             // chunked scores (126MB)
__device__ float g_Sm[BH*NM*NM];                // mem-attn scores (12.6MB)

static __device__ __forceinline__ unsigned f2u(float f) {
    unsigned u = __float_as_uint(f);
    return (u & 0x80000000u) ? ~u : (u | 0x80000000u);
}
static __device__ __forceinline__ float u2f(unsigned v) {
    return (v & 0x80000000u) ? __uint_as_float(v & 0x7fffffffu) : __uint_as_float(~v);
}

// ---------------- small dot kernels ----------------
__global__ __launch_bounds__(256) void low_qkv_kernel(const float* __restrict__ X,
                                                      const float* __restrict__ qkvA) {
    int row = blockIdx.x;
    __shared__ float xs[DIMC];
    for (int i = threadIdx.x; i < DIMC; i += 256) xs[i] = X[(size_t)row*DIMC + i];
    __syncthreads();
    int wid = threadIdx.x >> 5, lane = threadIdx.x & 31;
    for (int o = wid; o < 24; o += 8) {
        const float* a = qkvA + (size_t)o*DIMC;
        float s = 0.f;
        for (int c = lane; c < DIMC; c += 32) s += xs[c]*a[c];
        for (int off = 16; off; off >>= 1) s += __shfl_down_sync(0xffffffffu, s, off);
        if (lane == 0) g_low[row*24 + o] = s;
    }
}

__global__ __launch_bounds__(256) void id_lows_kernel(const float* __restrict__ IDT,
                                                      const float* __restrict__ idkA,
                                                      const float* __restrict__ idvA) {
    int row = blockIdx.x;
    __shared__ float xs[DIMC];
    for (int i = threadIdx.x; i < DIMC; i += 256) xs[i] = IDT[(size_t)row*DIMC + i];
    __syncthreads();
    int wid = threadIdx.x >> 5, lane = threadIdx.x & 31;
    for (int o = wid; o < 16; o += 8) {
        const float* a = (o < 8) ? (idkA + (size_t)o*DIMC) : (idvA + (size_t)(o-8)*DIMC);
        float s = 0.f;
        for (int c = lane; c < DIMC; c += 32) s += xs[c]*a[c];
        for (int off = 16; off; off >>= 1) s += __shfl_down_sync(0xffffffffu, s, off);
        if (lane == 0) {
            if (o < 8) g_idlowk[row*8 + o] = s;
            else       g_idlowv[row*8 + (o-8)] = s;
        }
    }
}

__global__ __launch_bounds__(256) void idk_kernel(const float* __restrict__ IDT,
                                                  const float* __restrict__ Widk,
                                                  const float* __restrict__ bidk,
                                                  const float* __restrict__ idkB) {
    int row = blockIdx.x;
    __shared__ float xs[DIMC];
    for (int i = threadIdx.x; i < DIMC; i += 256) xs[i] = IDT[(size_t)row*DIMC + i];
    __syncthreads();
    int wid = threadIdx.x >> 5, lane = threadIdx.x & 31;
    for (int o = wid; o < HEADS; o += 8) {
        const float* a = Widk + (size_t)o*DIMC;
        float s = 0.f;
        for (int c = lane; c < DIMC; c += 32) s += xs[c]*a[c];
        for (int off = 16; off; off >>= 1) s += __shfl_down_sync(0xffffffffu, s, off);
        if (lane == 0) {
            float l = 0.f;
            #pragma unroll
            for (int r = 0; r < 8; r++) l += g_idlowk[row*8 + r] * idkB[o*8 + r];
            g_IDK[row*HEADS + o] = s + bidk[o] + 0.125f*l;
        }
    }
}

__global__ __launch_bounds__(256) void coef_kernel(const float* __restrict__ routeW,
                                                   const float* __restrict__ projA) {
    int row = blockIdx.x;
    __shared__ float xs[DIMC];
    __shared__ float dots[36];
    __shared__ float routeS[4];
    for (int i = threadIdx.x; i < DIMC; i += 256) xs[i] = g_xo[(size_t)row*DIMC + i];
    __syncthreads();
    int wid = threadIdx.x >> 5, lane = threadIdx.x & 31;
    for (int o = wid; o < 36; o += 8) {
        const float* a = (o < 4) ? (routeW + (size_t)o*DIMC) : (projA + (size_t)(o-4)*DIMC);
        float s = 0.f;
        for (int c = lane; c < DIMC; c += 32) s += xs[c]*a[c];
        for (int off = 16; off; off >>= 1) s += __shfl_down_sync(0xffffffffu, s, off);
        if (lane == 0) dots[o] = s;
    }
    __syncthreads();
    if (threadIdx.x == 0) {
        float m = fmaxf(fmaxf(dots[0], dots[1]), fmaxf(dots[2], dots[3]));
        float e[4]; float s0 = 0.f;
        for (int i = 0; i < 4; i++) { e[i] = expf(dots[i]-m); s0 += e[i]; }
        for (int i = 0; i < 4; i++) routeS[i] = e[i]/s0;
    }
    __syncthreads();
    if (threadIdx.x < 32) {
        int t = threadIdx.x;
        g_coef[row*32 + t] = 0.125f * routeS[t >> 3] * dots[4 + t];
    }
}

// ---------------- GEMMs: 64x64x16 tiles, 4x4 microtile ----------------
__global__ __launch_bounds__(256) void gemm_qkv_kernel(const float* __restrict__ X,
                                                       const float* __restrict__ W,
                                                       const float* __restrict__ bias,
                                                       const float* __restrict__ qkvB) {
    __shared__ __align__(16) float As[16*68];
    __shared__ __align__(16) float Bs[16*68];
    int tid = threadIdx.x;
    int tx = tid & 15, ty = tid >> 4;
    int m0 = blockIdx.y * 64, n0 = blockIdx.x * 64;
    int lr = tid >> 2, lc = (tid & 3) * 4;
    float acc[4][4];
    #pragma unroll
    for (int i = 0; i < 4; i++)
        #pragma unroll
        for (int j = 0; j < 4; j++) acc[i][j] = 0.f;
    for (int k0 = 0; k0 < DIMC; k0 += 16) {
        float4 a4 = *(const float4*)(X + (size_t)(m0+lr)*DIMC + k0 + lc);
        float4 b4 = *(const float4*)(W + (size_t)(n0+lr)*DIMC + k0 + lc);
        As[(lc+0)*68+lr]=a4.x; As[(lc+1)*68+lr]=a4.y; As[(lc+2)*68+lr]=a4.z; As[(lc+3)*68+lr]=a4.w;
        Bs[(lc+0)*68+lr]=b4.x; Bs[(lc+1)*68+lr]=b4.y; Bs[(lc+2)*68+lr]=b4.z; Bs[(lc+3)*68+lr]=b4.w;
        __syncthreads();
        #pragma unroll
        for (int kk = 0; kk < 16; kk++) {
            float4 a = *(const float4*)&As[kk*68 + ty*4];
            float4 b = *(const float4*)&Bs[kk*68 + tx*4];
            float av[4] = {a.x,a.y,a.z,a.w}, bv[4] = {b.x,b.y,b.z,b.w};
            #pragma unroll
            for (int i = 0; i < 4; i++)
                #pragma unroll
                for (int j = 0; j < 4; j++) acc[i][j] += av[i]*bv[j];
        }
        __syncthreads();
    }
    #pragma unroll
    for (int i = 0; i < 4; i++) {
        int m = m0 + ty*4 + i;
        int bb = m / NTOK, nn = m % NTOK;
        const float* lowr = g_low + m*24;
        #pragma unroll
        for (int j = 0; j < 4; j++) {
            int n = n0 + tx*4 + j;
            int g = n / DIMC, c = n % DIMC;
            float v = acc[i][j] + bias[n];
            float l = 0.f;
            #pragma unroll
            for (int r = 0; r < 8; r++) l += lowr[g*8+r] * qkvB[((size_t)g*DIMC + c)*8 + r];
            v += 0.125f * l;
            int h = c >> 6, d = c & 63;
            size_t idx = (((size_t)bb*HEADS + h)*NTOK + nn)*HD + d;
            if (g == 0)      g_q[idx] = v * 0.125f;
            else if (g == 1) g_k[idx] = v;
            else             g_v[idx] = v;
        }
    }
}

__global__ __launch_bounds__(256) void gemm_idv_kernel(const float* __restrict__ X,
                                                       const float* __restrict__ W,
                                                       const float* __restrict__ bias,
                                                       const float* __restrict__ idvB) {
    __shared__ __align__(16) float As[16*68];
    __shared__ __align__(16) float Bs[16*68];
    int tid = threadIdx.x;
    int tx = tid & 15, ty = tid >> 4;
    int m0 = blockIdx.y * 64, n0 = blockIdx.x * 64;
    int lr = tid >> 2, lc = (tid & 3) * 4;
    float acc[4][4];
    #pragma unroll
    for (int i = 0; i < 4; i++)
        #pragma unroll
        for (int j = 0; j < 4; j++) acc[i][j] = 0.f;
    for (int k0 = 0; k0 < DIMC; k0 += 16) {
        float4 a4 = *(const float4*)(X + (size_t)(m0+lr)*DIMC + k0 + lc);
        float4 b4 = *(const float4*)(W + (size_t)(n0+lr)*DIMC + k0 + lc);
        As[(lc+0)*68+lr]=a4.x; As[(lc+1)*68+lr]=a4.y; As[(lc+2)*68+lr]=a4.z; As[(lc+3)*68+lr]=a4.w;
        Bs[(lc+0)*68+lr]=b4.x; Bs[(lc+1)*68+lr]=b4.y; Bs[(lc+2)*68+lr]=b4.z; Bs[(lc+3)*68+lr]=b4.w;
        __syncthreads();
        #pragma unroll
        for (int kk = 0; kk < 16; kk++) {
            float4 a = *(const float4*)&As[kk*68 + ty*4];
            float4 b = *(const float4*)&Bs[kk*68 + tx*4];
            float av[4] = {a.x,a.y,a.z,a.w}, bv[4] = {b.x,b.y,b.z,b.w};
            #pragma unroll
            for (int i = 0; i < 4; i++)
                #pragma unroll
                for (int j = 0; j < 4; j++) acc[i][j] += av[i]*bv[j];
        }
        __syncthreads();
    }
    #pragma unroll
    for (int i = 0; i < 4; i++) {
        int m = m0 + ty*4 + i;
        #pragma unroll
        for (int j = 0; j < 4; j++) {
            int c = n0 + tx*4 + j;
            float v = acc[i][j] + bias[c];
            float l = 0.f;
            #pragma unroll
            for (int r = 0; r < 8; r++) l += g_idlowv[m*8+r] * idvB[(size_t)c*8 + r];
            g_IDV[(size_t)m*DIMC + c] = v + 0.125f*l;
        }
    }
}

__global__ __launch_bounds__(256) void gemm_out_kernel(const float* __restrict__ W,
                                                       const float* __restrict__ bias,
                                                       const float* __restrict__ projB,
                                                       float* __restrict__ OUT) {
    __shared__ __align__(16) float As[16*68];
    __shared__ __align__(16) float Bs[16*68];
    int tid = threadIdx.x;
    int tx = tid & 15, ty = tid >> 4;
    int m0 = blockIdx.y * 64, n0 = blockIdx.x * 64;
    int lr = tid >> 2, lc = (tid & 3) * 4;
    float acc[4][4];
    #pragma unroll
    for (int i = 0; i < 4; i++)
        #pragma unroll
        for (int j = 0; j < 4; j++) acc[i][j] = 0.f;
    for (int k0 = 0; k0 < DIMC; k0 += 16) {
        float4 a4 = *(const float4*)(g_xo + (size_t)(m0+lr)*DIMC + k0 + lc);
        float4 b4 = *(const float4*)(W + (size_t)(n0+lr)*DIMC + k0 + lc);
        As[(lc+0)*68+lr]=a4.x; As[(lc+1)*68+lr]=a4.y; As[(lc+2)*68+lr]=a4.z; As[(lc+3)*68+lr]=a4.w;
        Bs[(lc+0)*68+lr]=b4.x; Bs[(lc+1)*68+lr]=b4.y; Bs[(lc+2)*68+lr]=b4.z; Bs[(lc+3)*68+lr]=b4.w;
        __syncthreads();
        #pragma unroll
        for (int kk = 0; kk < 16; kk++) {
            float4 a = *(const float4*)&As[kk*68 + ty*4];
            float4 b = *(const float4*)&Bs[kk*68 + tx*4];
            float av[4] = {a.x,a.y,a.z,a.w}, bv[4] = {b.x,b.y,b.z,b.w};
            #pragma unroll
            for (int i = 0; i < 4; i++)
                #pragma unroll
                for (int j = 0; j < 4; j++) acc[i][j] += av[i]*bv[j];
        }
        __syncthreads();
    }
    #pragma unroll
    for (int i = 0; i < 4; i++) {
        int m = m0 + ty*4 + i;
        const float* cf = g_coef + m*32;
        #pragma unroll
        for (int j = 0; j < 4; j++) {
            int c = n0 + tx*4 + j;
            float v = acc[i][j] + bias[c];
            float l = 0.f;
            #pragma unroll
            for (int er = 0; er < 32; er++) {
                int e = er >> 3, r = er & 7;
                l += cf[er] * projB[((size_t)e*DIMC + c)*8 + r];
            }
            OUT[(size_t)m*DIMC + c] = v + l;
        }
    }
}

// ---------------- build concatenated K/V + k_m_id/v_m_id outputs ----------------
__global__ __launch_bounds__(256) void build_kv_kernel(const float* __restrict__ memK,
                                                       const float* __restrict__ memV,
                                                       float* __restrict__ kmid,
                                                       float* __restrict__ vmid) {
    int t = blockIdx.x*256 + threadIdx.x;       // 48*2560*64
    int d = t & 63;
    int j = (t >> 6) % LFULL;
    int bh = (t >> 6) / LFULL;
    int b = bh / HEADS, h = bh % HEADS;
    float kv, vv;
    if (j < MEMN) {
        size_t src = ((size_t)bh*MEMN + j)*HD + d;
        kv = memK[src]; vv = memV[src];
    } else {
        int n = j - MEMN;
        size_t src = ((size_t)bh*NTOK + n)*HD + d;
        float kval = g_k[src], vval = g_v[src];
        kv = kval;
        if (n < NM) {
            float idk = g_IDK[(b*NM + n)*HEADS + h];
            float km = kval * (1.f + tanhf(idk));
            float vm = vval + g_IDV[((size_t)(b*NM + n))*DIMC + h*HD + d];
            size_t oidx = ((size_t)bh*NM + n)*HD + d;
            kmid[oidx] = km;
            vmid[oidx] = vm;
            vv = vm;
        } else {
            vv = vval;
        }
    }
    g_kf[t] = kv;
    g_vf[t] = vv;
}

// ---------------- score GEMMs (K=64) ----------------
__global__ __launch_bounds__(256) void score_gemm_s_kernel(int bh_off) {
    int bh = bh_off + blockIdx.z;
    const float* Ab = g_q + ((size_t)bh*NTOK + NM)*HD;
    const float* Bb = g_kf + (size_t)bh*LFULL*HD;
    float* Sb = g_Ss + (size_t)blockIdx.z*NS*LFULL;
    __shared__ __align__(16) float As[16*68];
    __shared__ __align__(16) float Bs[16*68];
    int tid = threadIdx.x;
    int tx = tid & 15, ty = tid >> 4;
    int m0 = blockIdx.y * 64, n0 = blockIdx.x * 64;
    int lr = tid >> 2, lc = (tid & 3) * 4;
    float acc[4][4];
    #pragma unroll
    for (int i = 0; i < 4; i++)
        #pragma unroll
        for (int j = 0; j < 4; j++) acc[i][j] = 0.f;
    #pragma unroll
    for (int k0 = 0; k0 < HD; k0 += 16) {
        float4 a4 = *(const float4*)(Ab + (size_t)(m0+lr)*HD + k0 + lc);
        float4 b4 = *(const float4*)(Bb + (size_t)(n0+lr)*HD + k0 + lc);
        As[(lc+0)*68+lr]=a4.x; As[(lc+1)*68+lr]=a4.y; As[(lc+2)*68+lr]=a4.z; As[(lc+3)*68+lr]=a4.w;
        Bs[(lc+0)*68+lr]=b4.x; Bs[(lc+1)*68+lr]=b4.y; Bs[(lc+2)*68+lr]=b4.z; Bs[(lc+3)*68+lr]=b4.w;
        __syncthreads();
        #pragma unroll
        for (int kk = 0; kk < 16; kk++) {
            float4 a = *(const float4*)&As[kk*68 + ty*4];
            float4 b = *(const float4*)&Bs[kk*68 + tx*4];
            float av[4] = {a.x,a.y,a.z,a.w}, bv[4] = {b.x,b.y,b.z,b.w};
            #pragma unroll
            for (int i = 0; i < 4; i++)
                #pragma unroll
                for (int j = 0; j < 4; j++) acc[i][j] += av[i]*bv[j];
        }
        __syncthreads();
    }
    #pragma unroll
    for (int i = 0; i < 4; i++) {
        int m = m0 + ty*4 + i;
        #pragma unroll
        for (int j = 0; j < 4; j++) {
            Sb[(size_t)m*LFULL + n0 + tx*4 + j] = acc[i][j];
        }
    }
}

__global__ __launch_bounds__(256) void score_gemm_m_kernel(const float* __restrict__ kmid) {
    int bh = blockIdx.z;
    const float* Ab = g_q + (size_t)bh*NTOK*HD;
    const float* Bb = kmid + (size_t)bh*NM*HD;
    float* Sb = g_Sm + (size_t)bh*NM*NM;
    __shared__ __align__(16) float As[16*68];
    __shared__ __align__(16) float Bs[16*68];
    int tid = threadIdx.x;
    int tx = tid & 15, ty = tid >> 4;
    int m0 = blockIdx.y * 64, n0 = blockIdx.x * 64;
    int lr = tid >> 2, lc = (tid & 3) * 4;
    float acc[4][4];
    #pragma unroll
    for (int i = 0; i < 4; i++)
        #pragma unroll
        for (int j = 0; j < 4; j++) acc[i][j] = 0.f;
    #pragma unroll
    for (int k0 = 0; k0 < HD; k0 += 16) {
        float4 a4 = *(const float4*)(Ab + (size_t)(m0+lr)*HD + k0 + lc);
        float4 b4 = *(const float4*)(Bb + (size_t)(n0+lr)*HD + k0 + lc);
        As[(lc+0)*68+lr]=a4.x; As[(lc+1)*68+lr]=a4.y; As[(lc+2)*68+lr]=a4.z; As[(lc+3)*68+lr]=a4.w;
        Bs[(lc+0)*68+lr]=b4.x; Bs[(lc+1)*68+lr]=b4.y; Bs[(lc+2)*68+lr]=b4.z; Bs[(lc+3)*68+lr]=b4.w;
        __syncthreads();
        #pragma unroll
        for (int kk = 0; kk < 16; kk++) {
            float4 a = *(const float4*)&As[kk*68 + ty*4];
            float4 b = *(const float4*)&Bs[kk*68 + tx*4];
            float av[4] = {a.x,a.y,a.z,a.w}, bv[4] = {b.x,b.y,b.z,b.w};
            #pragma unroll
            for (int i = 0; i < 4; i++)
                #pragma unroll
                for (int j = 0; j < 4; j++) acc[i][j] += av[i]*bv[j];
        }
        __syncthreads();
    }
    #pragma unroll
    for (int i = 0; i < 4; i++) {
        int m = m0 + ty*4 + i;
        #pragma unroll
        for (int j = 0; j < 4; j++) {
            Sb[(size_t)m*NM + n0 + tx*4 + j] = acc[i][j];
        }
    }
}

// ---------------- fused topk+softmax+AV: memory attention ----------------
__global__ __launch_bounds__(256) void topk_m_kernel(const float* __restrict__ VM) {
    int bid = blockIdx.x;
    int qm = bid & 255, bh = bid >> 8;
    int b = bh / HEADS, h = bh % HEADS;
    __shared__ float sc[NM];
    __shared__ int s_cnt32[33];
    __shared__ int s_eqw[8];
    __shared__ unsigned s_redu[8];
    __shared__ float s_redf[8];
    __shared__ float s_part[4][HD];
    int tid = threadIdx.x, lane = tid & 31, wid = tid >> 5;
    float s = g_Sm[((size_t)bh*NM + qm)*NM + tid];
    unsigned u = f2u(s);
    if (tid < 33) s_cnt32[tid] = 0;
    __syncthreads();
    unsigned T = 0u;
    for (int bit = 31; bit >= 0; bit--) {
        unsigned cand = T | (1u << bit);
        int c = (u >= cand) ? 1 : 0;
        c = __reduce_add_sync(0xffffffffu, c);
        if (lane == 0) atomicAdd(&s_cnt32[bit], c);
        __syncthreads();
        if (s_cnt32[bit] >= KSEL_M) T = cand;
    }
    {
        int c = (u > T) ? 1 : 0;
        c = __reduce_add_sync(0xffffffffu, c);
        if (lane == 0) atomicAdd(&s_cnt32[32], c);
    }
    unsigned baleq = __ballot_sync(0xffffffffu, u == T);
    if (lane == 0) s_eqw[wid] = __popc(baleq);
    unsigned umax = __reduce_max_sync(0xffffffffu, u);
    if (lane == 0) s_redu[wid] = umax;
    __syncthreads();
    int need = KSEL_M - s_cnt32[32];
    int off = 0;
    for (int w = 0; w < wid; w++) off += s_eqw[w];
    int rank = off + __popc(baleq & ((1u << lane) - 1u));
    bool sel = (u > T) || ((u == T) && rank < need);
    unsigned um = s_redu[0];
    for (int w = 1; w < 8; w++) um = max(um, s_redu[w]);
    float smax = u2f(um);
    float e = sel ? expf(s - smax) : 0.f;
    float ss = e;
    for (int o = 16; o; o >>= 1) ss += __shfl_xor_sync(0xffffffffu, ss, o);
    if (lane == 0) s_redf[wid] = ss;
    __syncthreads();
    float tot = 0.f;
    for (int w = 0; w < 8; w++) tot += s_redf[w];
    float inv = 1.f / tot;
    sc[tid] = e * inv;
    __syncthreads();
    int d = tid & 63, grp = tid >> 6;
    float acc = 0.f;
    for (int j = grp; j < NM; j += 4) {
        float w = sc[j];
        if (w != 0.f) acc += w * VM[((size_t)bh*NM + j)*HD + d];
    }
    s_part[grp][d] = acc;
    __syncthreads();
    if (tid < HD) {
        float o4 = s_part[0][tid] + s_part[1][tid] + s_part[2][tid] + s_part[3][tid];
        g_xo[((size_t)b*NTOK + qm)*DIMC + h*HD + tid] = o4;
    }
}

// ---------------- fused topk+softmax+AV: full-sequence attention ----------------
__global__ __launch_bounds__(256) void topk_s_kernel(int bh_off) {
    int bid = blockIdx.x;
    int qs = bid & 1023, bh_local = bid >> 10;
    int bh = bh_off + bh_local;
    int b = bh / HEADS, h = bh % HEADS;
    __shared__ float sc[LFULL];
    __shared__ int s_cnt32[33];
    __shared__ int s_eqw[80];
    __shared__ unsigned s_redu[8];
    __shared__ float s_redf[8];
    __shared__ float s_part[4][HD];
    int tid = threadIdx.x, lane = tid & 31, wid = tid >> 5;
    const float* Srow = g_Ss + ((size_t)bh_local*NS + qs)*LFULL;
    float sv[10]; unsigned uk[10];
    #pragma unroll
    for (int i = 0; i < 10; i++) {
        float s = Srow[i*256 + tid];
        sv[i] = s; uk[i] = f2u(s);
    }
    if (tid < 33) s_cnt32[tid] = 0;
    __syncthreads();
    unsigned T = 0u;
    for (int bit = 31; bit >= 0; bit--) {
        unsigned cand = T | (1u << bit);
        int c = 0;
        #pragma unroll
        for (int i = 0; i < 10; i++) c += (uk[i] >= cand);
        c = __reduce_add_sync(0xffffffffu, c);
        if (lane == 0) atomicAdd(&s_cnt32[bit], c);
        __syncthreads();
        if (s_cnt32[bit] >= KSEL_S) T = cand;
    }
    {
        int c = 0;
        #pragma unroll
        for (int i = 0; i < 10; i++) c += (uk[i] > T);
        c = __reduce_add_sync(0xffffffffu, c);
        if (lane == 0) atomicAdd(&s_cnt32[32], c);
    }
    unsigned balv[10];
    #pragma unroll
    for (int i = 0; i < 10; i++) {
        balv[i] = __ballot_sync(0xffffffffu, uk[i] == T);
        if (lane == 0) s_eqw[i*8 + wid] = __popc(balv[i]);
    }
    unsigned umax = uk[0];
    #pragma unroll
    for (int i = 1; i < 10; i++) umax = max(umax, uk[i]);
    umax = __reduce_max_sync(0xffffffffu, umax);
    if (lane == 0) s_redu[wid] = umax;
    __syncthreads();
    int need = KSEL_S - s_cnt32[32];
    unsigned ltm = (1u << lane) - 1u;
    bool sel[10];
    int run = 0;
    #pragma unroll
    for (int i = 0; i < 10; i++) {
        int offw = 0, tot = 0;
        #pragma unroll
        for (int w = 0; w < 8; w++) { int cc = s_eqw[i*8 + w]; if (w < wid) offw += cc; tot += cc; }
        int rank = run + offw + __popc(balv[i] & ltm);
        sel[i] = (uk[i] > T) || ((uk[i] == T) && rank < need);
        run += tot;
    }
    unsigned um = s_redu[0];
    for (int w = 1; w < 8; w++) um = max(um, s_redu[w]);
    float smax = u2f(um);
    float esum = 0.f; float ev[10];
    #pragma unroll
    for (int i = 0; i < 10; i++) { ev[i] = sel[i] ? expf(sv[i]-smax) : 0.f; esum += ev[i]; }
    for (int o = 16; o; o >>= 1) esum += __shfl_xor_sync(0xffffffffu, esum, o);
    if (lane == 0) s_redf[wid] = esum;
    __syncthreads();
    float tot = 0.f;
    for (int w = 0; w < 8; w++) tot += s_redf[w];
    float inv = 1.f / tot;
    #pragma unroll
    for (int i = 0; i < 10; i++) sc[i*256 + tid] = ev[i]*inv;
    __syncthreads();
    int d = tid & 63, grp = tid >> 6;
    const float* vb = g_vf + (size_t)bh*LFULL*HD;
    float acc = 0.f;
    for (int j = grp; j < LFULL; j += 4) {
        float w = sc[j];
        if (w != 0.f) acc += w * vb[(size_t)j*HD + d];
    }
    s_part[grp][d] = acc;
    __syncthreads();
    if (tid < HD) {
        float o4 = s_part[0][tid] + s_part[1][tid] + s_part[2][tid] + s_part[3][tid];
        g_xo[((size_t)b*NTOK + NM + qs)*DIMC + h*HD + tid] = o4;
    }
}

// ---------------- launch ----------------
extern "C" void kernel_launch(void* const* d_in, const int* in_sizes, int n_in,
                              void* d_out, int out_size) {
    const float* x        = (const float*)d_in[0];
    const float* id_total = (const float*)d_in[1];
    const float* mem_k    = (const float*)d_in[2];
    const float* mem_v    = (const float*)d_in[3];
    const float* W_qkv    = (const float*)d_in[4];
    const float* b_qkv    = (const float*)d_in[5];
    const float* qkv_A    = (const float*)d_in[6];
    const float* qkv_B    = (const float*)d_in[7];
    const float* W_proj   = (const float*)d_in[8];
    const float* b_proj   = (const float*)d_in[9];
    const float* route_W  = (const float*)d_in[10];
    const float* proj_A   = (const float*)d_in[11];
    const float* proj_B   = (const float*)d_in[12];
    const float* W_idk    = (const float*)d_in[13];
    const float* b_idk    = (const float*)d_in[14];
    const float* idk_A    = (const float*)d_in[15];
    const float* idk_B    = (const float*)d_in[16];
    const float* W_idv    = (const float*)d_in[17];
    const float* b_idv    = (const float*)d_in[18];
    const float* idv_A    = (const float*)d_in[19];
    const float* idv_B    = (const float*)d_in[20];
    (void)in_sizes; (void)n_in; (void)out_size;

    float* out  = (float*)d_out;
    float* kmid = out + (size_t)Bsz*NTOK*DIMC;
    float* vmid = kmid + (size_t)BH*NM*HD;

    low_qkv_kernel<<<Bsz*NTOK, 256>>>(x, qkv_A);
    id_lows_kernel<<<Bsz*NM, 256>>>(id_total, idk_A, idv_A);
    gemm_qkv_kernel<<<dim3(36, 80), 256>>>(x, W_qkv, b_qkv, qkv_B);
    gemm_idv_kernel<<<dim3(12, 16), 256>>>(id_total, W_idv, b_idv, idv_B);
    idk_kernel<<<Bsz*NM, 256>>>(id_total, W_idk, b_idk, idk_B);
    build_kv_kernel<<<(BH*LFULL*HD)/256, 256>>>(mem_k, mem_v, kmid, vmid);
    score_gemm_m_kernel<<<dim3(4, 4, BH), 256>>>(kmid);
    topk_m_kernel<<<BH*NM, 256>>>(vmid);
    for (int c = 0; c < BH/CH; c++) {
        score_gemm_s_kernel<<<dim3(40, 16, CH), 256>>>(c*CH);
        topk_s_kernel<<<CH*NS, 256>>>(c*CH);
    }
    coef_kernel<<<Bsz*NTOK, 256>>>(route_W, proj_A);
    gemm_out_kernel<<<dim3(12, 80), 256>>>(W_proj, b_proj, proj_B, out);
}

// round 5
// speedup vs baseline: 4.2365x; 1.5330x over previous
#include <cuda_runtime.h>
#include <math.h>

#define Bsz   4
#define NTOK  1280
#define NM    256
#define NS    1024
#define DIMC  768
#define HEADS 12
#define HD    64
#define MEMN  1280
#define LFULL 2560
#define KSEL_M 128
#define KSEL_S 640
#define BH    (Bsz*HEADS)
#define CH    12            // bh per score chunk

// ---------------- scratch (device globals; no allocation) ----------------
__device__ float g_low[Bsz*NTOK*24];
__device__ float g_q[BH*NTOK*HD];               // pre-scaled by D^-0.5
__device__ float g_k[BH*NTOK*HD];
__device__ float g_v[BH*NTOK*HD];
__device__ float g_idlowk[Bsz*NM*8];
__device__ float g_idlowv[Bsz*NM*8];
__device__ float g_IDK[Bsz*NM*HEADS];
__device__ float g_IDV[Bsz*NM*DIMC];
__device__ float g_xo[Bsz*NTOK*DIMC];
__device__ float g_coef[Bsz*NTOK*32];
__device__ float g_kf[BH*LFULL*HD];             // concat K (47MB)
__device__ float g_vf[BH*LFULL*HD];             // concat V (47MB)
__device__ float g_Ss[CH*NS*LFULL];             // chunked scores (126MB)
__device__ float g_Sm[BH*NM*NM];                // mem-attn scores (12.6MB)

static __device__ __forceinline__ unsigned f2u(float f) {
    unsigned u = __float_as_uint(f);
    return (u & 0x80000000u) ? ~u : (u | 0x80000000u);
}
static __device__ __forceinline__ float u2f(unsigned v) {
    return (v & 0x80000000u) ? __uint_as_float(v & 0x7fffffffu) : __uint_as_float(~v);
}

// ---------------- radix-256 top-k threshold (4 passes, 3 barriers each) ----
// Finds T = KSEL-th largest key (as ordered uint) and cnt_gt = #keys > T.
template<int NPT, int KSEL>
static __device__ __forceinline__ void radix_topk(const unsigned* uk, int tid, int lane, int wid,
                                                  int* hist, int* aux, unsigned& T, int& cnt_gt) {
    unsigned prefix = 0;
    int base = 0;
    #pragma unroll
    for (int p = 3; p >= 0; p--) {
        int sh = p*8;
        hist[tid] = 0;
        __syncthreads();
        unsigned himask = (p == 3) ? 0u : (0xffffffffu << (sh+8));
        #pragma unroll
        for (int i = 0; i < NPT; i++)
            if ((uk[i] & himask) == prefix) atomicAdd(&hist[(uk[i] >> sh) & 255], 1);
        __syncthreads();
        int v = 255 - tid;
        int val = hist[v];
        int incl = val;
        #pragma unroll
        for (int o = 1; o < 32; o <<= 1) {
            int n = __shfl_up_sync(0xffffffffu, incl, o);
            if (lane >= o) incl += n;
        }
        if (lane == 31) aux[wid] = incl;
        __syncthreads();
        int woff = 0;
        #pragma unroll
        for (int w = 0; w < 8; w++) if (w < wid) woff += aux[w];
        incl += woff;
        int strict = incl - val;
        if (base + strict < KSEL && KSEL <= base + incl) { aux[8] = v; aux[9] = base + strict; }
        __syncthreads();
        prefix |= ((unsigned)aux[8]) << sh;
        base = aux[9];
    }
    T = prefix; cnt_gt = base;
}

// ---------------- small dot kernels ----------------
__global__ __launch_bounds__(256) void low_qkv_kernel(const float* __restrict__ X,
                                                      const float* __restrict__ qkvA) {
    int row = blockIdx.x;
    __shared__ float xs[DIMC];
    for (int i = threadIdx.x; i < DIMC; i += 256) xs[i] = X[(size_t)row*DIMC + i];
    __syncthreads();
    int wid = threadIdx.x >> 5, lane = threadIdx.x & 31;
    for (int o = wid; o < 24; o += 8) {
        const float* a = qkvA + (size_t)o*DIMC;
        float s = 0.f;
        for (int c = lane; c < DIMC; c += 32) s += xs[c]*a[c];
        for (int off = 16; off; off >>= 1) s += __shfl_down_sync(0xffffffffu, s, off);
        if (lane == 0) g_low[row*24 + o] = s;
    }
}

__global__ __launch_bounds__(256) void id_lows_kernel(const float* __restrict__ IDT,
                                                      const float* __restrict__ idkA,
                                                      const float* __restrict__ idvA) {
    int row = blockIdx.x;
    __shared__ float xs[DIMC];
    for (int i = threadIdx.x; i < DIMC; i += 256) xs[i] = IDT[(size_t)row*DIMC + i];
    __syncthreads();
    int wid = threadIdx.x >> 5, lane = threadIdx.x & 31;
    for (int o = wid; o < 16; o += 8) {
        const float* a = (o < 8) ? (idkA + (size_t)o*DIMC) : (idvA + (size_t)(o-8)*DIMC);
        float s = 0.f;
        for (int c = lane; c < DIMC; c += 32) s += xs[c]*a[c];
        for (int off = 16; off; off >>= 1) s += __shfl_down_sync(0xffffffffu, s, off);
        if (lane == 0) {
            if (o < 8) g_idlowk[row*8 + o] = s;
            else       g_idlowv[row*8 + (o-8)] = s;
        }
    }
}

__global__ __launch_bounds__(256) void idk_kernel(const float* __restrict__ IDT,
                                                  const float* __restrict__ Widk,
                                                  const float* __restrict__ bidk,
                                                  const float* __restrict__ idkB) {
    int row = blockIdx.x;
    __shared__ float xs[DIMC];
    for (int i = threadIdx.x; i < DIMC; i += 256) xs[i] = IDT[(size_t)row*DIMC + i];
    __syncthreads();
    int wid = threadIdx.x >> 5, lane = threadIdx.x & 31;
    for (int o = wid; o < HEADS; o += 8) {
        const float* a = Widk + (size_t)o*DIMC;
        float s = 0.f;
        for (int c = lane; c < DIMC; c += 32) s += xs[c]*a[c];
        for (int off = 16; off; off >>= 1) s += __shfl_down_sync(0xffffffffu, s, off);
        if (lane == 0) {
            float l = 0.f;
            #pragma unroll
            for (int r = 0; r < 8; r++) l += g_idlowk[row*8 + r] * idkB[o*8 + r];
            g_IDK[row*HEADS + o] = s + bidk[o] + 0.125f*l;
        }
    }
}

__global__ __launch_bounds__(256) void coef_kernel(const float* __restrict__ routeW,
                                                   const float* __restrict__ projA) {
    int row = blockIdx.x;
    __shared__ float xs[DIMC];
    __shared__ float dots[36];
    __shared__ float routeS[4];
    for (int i = threadIdx.x; i < DIMC; i += 256) xs[i] = g_xo[(size_t)row*DIMC + i];
    __syncthreads();
    int wid = threadIdx.x >> 5, lane = threadIdx.x & 31;
    for (int o = wid; o < 36; o += 8) {
        const float* a = (o < 4) ? (routeW + (size_t)o*DIMC) : (projA + (size_t)(o-4)*DIMC);
        float s = 0.f;
        for (int c = lane; c < DIMC; c += 32) s += xs[c]*a[c];
        for (int off = 16; off; off >>= 1) s += __shfl_down_sync(0xffffffffu, s, off);
        if (lane == 0) dots[o] = s;
    }
    __syncthreads();
    if (threadIdx.x == 0) {
        float m = fmaxf(fmaxf(dots[0], dots[1]), fmaxf(dots[2], dots[3]));
        float e[4]; float s0 = 0.f;
        for (int i = 0; i < 4; i++) { e[i] = expf(dots[i]-m); s0 += e[i]; }
        for (int i = 0; i < 4; i++) routeS[i] = e[i]/s0;
    }
    __syncthreads();
    if (threadIdx.x < 32) {
        int t = threadIdx.x;
        g_coef[row*32 + t] = 0.125f * routeS[t >> 3] * dots[4 + t];
    }
}

// ---------------- GEMM core macro: 64x64 tile, 4x4 micro, reg prefetch -----
#define GEMM_BODY(APTR, BPTR, ALD, BLD, KDIM)                                        \
    __shared__ __align__(16) float As[16*68];                                        \
    __shared__ __align__(16) float Bs[16*68];                                        \
    int tid = threadIdx.x;                                                           \
    int tx = tid & 15, ty = tid >> 4;                                                \
    int lr = tid >> 2, lc = (tid & 3) * 4;                                           \
    float acc[4][4];                                                                 \
    _Pragma("unroll")                                                                \
    for (int i = 0; i < 4; i++)                                                      \
        _Pragma("unroll")                                                            \
        for (int j = 0; j < 4; j++) acc[i][j] = 0.f;                                 \
    float4 a4 = *(const float4*)((APTR) + (size_t)(m0+lr)*(ALD) + lc);               \
    float4 b4 = *(const float4*)((BPTR) + (size_t)(n0+lr)*(BLD) + lc);               \
    for (int k0 = 0; k0 < (KDIM); k0 += 16) {                                        \
        As[(lc+0)*68+lr]=a4.x; As[(lc+1)*68+lr]=a4.y;                                \
        As[(lc+2)*68+lr]=a4.z; As[(lc+3)*68+lr]=a4.w;                                \
        Bs[(lc+0)*68+lr]=b4.x; Bs[(lc+1)*68+lr]=b4.y;                                \
        Bs[(lc+2)*68+lr]=b4.z; Bs[(lc+3)*68+lr]=b4.w;                                \
        __syncthreads();                                                             \
        int kn = (k0 + 16 < (KDIM)) ? (k0 + 16) : k0;                                \
        a4 = *(const float4*)((APTR) + (size_t)(m0+lr)*(ALD) + kn + lc);             \
        b4 = *(const float4*)((BPTR) + (size_t)(n0+lr)*(BLD) + kn + lc);             \
        _Pragma("unroll")                                                            \
        for (int kk = 0; kk < 16; kk++) {                                            \
            float4 a = *(const float4*)&As[kk*68 + ty*4];                            \
            float4 b = *(const float4*)&Bs[kk*68 + tx*4];                            \
            float av[4] = {a.x,a.y,a.z,a.w}, bv[4] = {b.x,b.y,b.z,b.w};              \
            _Pragma("unroll")                                                        \
            for (int i = 0; i < 4; i++)                                              \
                _Pragma("unroll")                                                    \
                for (int j = 0; j < 4; j++) acc[i][j] += av[i]*bv[j];                \
        }                                                                            \
        __syncthreads();                                                             \
    }

__global__ __launch_bounds__(256) void gemm_qkv_kernel(const float* __restrict__ X,
                                                       const float* __restrict__ W,
                                                       const float* __restrict__ bias,
                                                       const float* __restrict__ qkvB) {
    int m0 = blockIdx.y * 64, n0 = blockIdx.x * 64;
    GEMM_BODY(X, W, DIMC, DIMC, DIMC)
    #pragma unroll
    for (int i = 0; i < 4; i++) {
        int m = m0 + ty*4 + i;
        int bb = m / NTOK, nn = m % NTOK;
        const float* lowr = g_low + m*24;
        #pragma unroll
        for (int j = 0; j < 4; j++) {
            int n = n0 + tx*4 + j;
            int g = n / DIMC, c = n % DIMC;
            float v = acc[i][j] + bias[n];
            float l = 0.f;
            #pragma unroll
            for (int r = 0; r < 8; r++) l += lowr[g*8+r] * qkvB[((size_t)g*DIMC + c)*8 + r];
            v += 0.125f * l;
            int h = c >> 6, d = c & 63;
            size_t idx = (((size_t)bb*HEADS + h)*NTOK + nn)*HD + d;
            if (g == 0)      g_q[idx] = v * 0.125f;
            else if (g == 1) g_k[idx] = v;
            else             g_v[idx] = v;
        }
    }
}

__global__ __launch_bounds__(256) void gemm_idv_kernel(const float* __restrict__ X,
                                                       const float* __restrict__ W,
                                                       const float* __restrict__ bias,
                                                       const float* __restrict__ idvB) {
    int m0 = blockIdx.y * 64, n0 = blockIdx.x * 64;
    GEMM_BODY(X, W, DIMC, DIMC, DIMC)
    #pragma unroll
    for (int i = 0; i < 4; i++) {
        int m = m0 + ty*4 + i;
        #pragma unroll
        for (int j = 0; j < 4; j++) {
            int c = n0 + tx*4 + j;
            float v = acc[i][j] + bias[c];
            float l = 0.f;
            #pragma unroll
            for (int r = 0; r < 8; r++) l += g_idlowv[m*8+r] * idvB[(size_t)c*8 + r];
            g_IDV[(size_t)m*DIMC + c] = v + 0.125f*l;
        }
    }
}

__global__ __launch_bounds__(256) void gemm_out_kernel(const float* __restrict__ W,
                                                       const float* __restrict__ bias,
                                                       const float* __restrict__ projB,
                                                       float* __restrict__ OUT) {
    int m0 = blockIdx.y * 64, n0 = blockIdx.x * 64;
    GEMM_BODY(g_xo, W, DIMC, DIMC, DIMC)
    #pragma unroll
    for (int i = 0; i < 4; i++) {
        int m = m0 + ty*4 + i;
        const float* cf = g_coef + m*32;
        #pragma unroll
        for (int j = 0; j < 4; j++) {
            int c = n0 + tx*4 + j;
            float v = acc[i][j] + bias[c];
            float l = 0.f;
            #pragma unroll
            for (int er = 0; er < 32; er++) {
                int e = er >> 3, r = er & 7;
                l += cf[er] * projB[((size_t)e*DIMC + c)*8 + r];
            }
            OUT[(size_t)m*DIMC + c] = v + l;
        }
    }
}

// ---------------- build concatenated K/V + k_m_id/v_m_id outputs ----------------
__global__ __launch_bounds__(256) void build_kv_kernel(const float* __restrict__ memK,
                                                       const float* __restrict__ memV,
                                                       float* __restrict__ kmid,
                                                       float* __restrict__ vmid) {
    int t = blockIdx.x*256 + threadIdx.x;
    int d = t & 63;
    int j = (t >> 6) % LFULL;
    int bh = (t >> 6) / LFULL;
    int b = bh / HEADS, h = bh % HEADS;
    float kv, vv;
    if (j < MEMN) {
        size_t src = ((size_t)bh*MEMN + j)*HD + d;
        kv = memK[src]; vv = memV[src];
    } else {
        int n = j - MEMN;
        size_t src = ((size_t)bh*NTOK + n)*HD + d;
        float kval = g_k[src], vval = g_v[src];
        kv = kval;
        if (n < NM) {
            float idk = g_IDK[(b*NM + n)*HEADS + h];
            float km = kval * (1.f + tanhf(idk));
            float vm = vval + g_IDV[((size_t)(b*NM + n))*DIMC + h*HD + d];
            size_t oidx = ((size_t)bh*NM + n)*HD + d;
            kmid[oidx] = km;
            vmid[oidx] = vm;
            vv = vm;
        } else {
            vv = vval;
        }
    }
    g_kf[t] = kv;
    g_vf[t] = vv;
}

// ---------------- score GEMMs (K=64) ----------------
__global__ __launch_bounds__(256) void score_gemm_s_kernel(int bh_off) {
    int bh = bh_off + blockIdx.z;
    const float* Ab = g_q + ((size_t)bh*NTOK + NM)*HD;
    const float* Bb = g_kf + (size_t)bh*LFULL*HD;
    float* Sb = g_Ss + (size_t)blockIdx.z*NS*LFULL;
    int m0 = blockIdx.y * 64, n0 = blockIdx.x * 64;
    GEMM_BODY(Ab, Bb, HD, HD, HD)
    #pragma unroll
    for (int i = 0; i < 4; i++) {
        int m = m0 + ty*4 + i;
        #pragma unroll
        for (int j = 0; j < 4; j++)
            Sb[(size_t)m*LFULL + n0 + tx*4 + j] = acc[i][j];
    }
}

__global__ __launch_bounds__(256) void score_gemm_m_kernel(const float* __restrict__ kmid) {
    int bh = blockIdx.z;
    const float* Ab = g_q + (size_t)bh*NTOK*HD;
    const float* Bb = kmid + (size_t)bh*NM*HD;
    float* Sb = g_Sm + (size_t)bh*NM*NM;
    int m0 = blockIdx.y * 64, n0 = blockIdx.x * 64;
    GEMM_BODY(Ab, Bb, HD, HD, HD)
    #pragma unroll
    for (int i = 0; i < 4; i++) {
        int m = m0 + ty*4 + i;
        #pragma unroll
        for (int j = 0; j < 4; j++)
            Sb[(size_t)m*NM + n0 + tx*4 + j] = acc[i][j];
    }
}

// ---------------- fused topk+softmax+AV: memory attention ----------------
__global__ __launch_bounds__(256) void topk_m_kernel(const float* __restrict__ VM) {
    int bid = blockIdx.x;
    int qm = bid & 255, bh = bid >> 8;
    int b = bh / HEADS, h = bh % HEADS;
    __shared__ int s_hist[256];
    __shared__ int s_aux[16];
    __shared__ float s_auxf[8];
    __shared__ int s_seg[8];
    __shared__ int s_pref[8];
    __shared__ int s_idx[KSEL_M];
    __shared__ float s_wt[KSEL_M];
    __shared__ float s_part[4][HD];
    int tid = threadIdx.x, lane = tid & 31, wid = tid >> 5;
    float s = g_Sm[((size_t)bh*NM + qm)*NM + tid];
    unsigned u = f2u(s);
    unsigned uk1[1] = {u};
    unsigned T; int cnt_gt;
    radix_topk<1, KSEL_M>(uk1, tid, lane, wid, s_hist, s_aux, T, cnt_gt);
    int need = KSEL_M - cnt_gt;
    unsigned ltm = (1u << lane) - 1u;
    unsigned baleq = __ballot_sync(0xffffffffu, u == T);
    unsigned umax = u;
    #pragma unroll
    for (int o = 16; o; o >>= 1) umax = max(umax, __shfl_xor_sync(0xffffffffu, umax, o));
    if (lane == 0) { s_seg[wid] = __popc(baleq); s_aux[wid] = (int)umax; }
    __syncthreads();
    if (tid < 8) { int p = 0; for (int q = 0; q < tid; q++) p += s_seg[q]; s_pref[tid] = p; }
    unsigned um = (unsigned)s_aux[0];
    #pragma unroll
    for (int w = 1; w < 8; w++) um = max(um, (unsigned)s_aux[w]);
    float smax = u2f(um);
    __syncthreads();
    int rank = s_pref[wid] + __popc(baleq & ltm);
    bool sel = (u > T) || ((u == T) && rank < need);
    float e = sel ? expf(s - smax) : 0.f;
    float ss = e;
    #pragma unroll
    for (int o = 16; o; o >>= 1) ss += __shfl_xor_sync(0xffffffffu, ss, o);
    if (lane == 0) s_auxf[wid] = ss;
    __syncthreads();
    float tot = 0.f;
    #pragma unroll
    for (int w = 0; w < 8; w++) tot += s_auxf[w];
    float inv = 1.f / tot;
    // compaction
    unsigned bals = __ballot_sync(0xffffffffu, sel);
    if (lane == 0) s_seg[wid] = __popc(bals);
    __syncthreads();
    if (tid < 8) { int p = 0; for (int q = 0; q < tid; q++) p += s_seg[q]; s_pref[tid] = p; }
    __syncthreads();
    if (sel) {
        int pos = s_pref[wid] + __popc(bals & ltm);
        s_idx[pos] = tid;
        s_wt[pos] = e * inv;
    }
    __syncthreads();
    int d = tid & 63, grp = tid >> 6;
    const float* vb = VM + (size_t)bh*NM*HD;
    float acc = 0.f;
    for (int e2 = grp; e2 < KSEL_M; e2 += 4)
        acc += s_wt[e2] * vb[(size_t)s_idx[e2]*HD + d];
    s_part[grp][d] = acc;
    __syncthreads();
    if (tid < HD) {
        float o4 = s_part[0][tid] + s_part[1][tid] + s_part[2][tid] + s_part[3][tid];
        g_xo[((size_t)b*NTOK + qm)*DIMC + h*HD + tid] = o4;
    }
}

// ---------------- fused topk+softmax+AV: full-sequence attention ----------------
__global__ __launch_bounds__(256) void topk_s_kernel(int bh_off) {
    int bid = blockIdx.x;
    int qs = bid & 1023, bh_local = bid >> 10;
    int bh = bh_off + bh_local;
    int b = bh / HEADS, h = bh % HEADS;
    __shared__ int s_hist[256];
    __shared__ int s_aux[16];
    __shared__ float s_auxf[8];
    __shared__ int s_seg[80];
    __shared__ int s_pref[80];
    __shared__ int s_idx[KSEL_S];
    __shared__ float s_wt[KSEL_S];
    __shared__ float s_part[4][HD];
    int tid = threadIdx.x, lane = tid & 31, wid = tid >> 5;
    const float* Srow = g_Ss + ((size_t)bh_local*NS + qs)*LFULL;
    float sv[10]; unsigned uk[10];
    #pragma unroll
    for (int i = 0; i < 10; i++) {
        float s = Srow[i*256 + tid];
        sv[i] = s; uk[i] = f2u(s);
    }
    unsigned T; int cnt_gt;
    radix_topk<10, KSEL_S>(uk, tid, lane, wid, s_hist, s_aux, T, cnt_gt);
    int need = KSEL_S - cnt_gt;
    unsigned ltm = (1u << lane) - 1u;
    unsigned balv[10];
    unsigned umax = uk[0];
    #pragma unroll
    for (int i = 1; i < 10; i++) umax = max(umax, uk[i]);
    #pragma unroll
    for (int o = 16; o; o >>= 1) umax = max(umax, __shfl_xor_sync(0xffffffffu, umax, o));
    #pragma unroll
    for (int i = 0; i < 10; i++) {
        balv[i] = __ballot_sync(0xffffffffu, uk[i] == T);
        if (lane == 0) s_seg[i*8 + wid] = __popc(balv[i]);
    }
    if (lane == 0) s_aux[wid] = (int)umax;
    __syncthreads();
    if (tid < 80) { int p = 0; for (int q = 0; q < tid; q++) p += s_seg[q]; s_pref[tid] = p; }
    unsigned um = (unsigned)s_aux[0];
    #pragma unroll
    for (int w = 1; w < 8; w++) um = max(um, (unsigned)s_aux[w]);
    float smax = u2f(um);
    __syncthreads();
    bool sel[10];
    float ev[10]; float esum = 0.f;
    #pragma unroll
    for (int i = 0; i < 10; i++) {
        int rank = s_pref[i*8 + wid] + __popc(balv[i] & ltm);
        sel[i] = (uk[i] > T) || ((uk[i] == T) && rank < need);
        ev[i] = sel[i] ? expf(sv[i] - smax) : 0.f;
        esum += ev[i];
    }
    #pragma unroll
    for (int o = 16; o; o >>= 1) esum += __shfl_xor_sync(0xffffffffu, esum, o);
    if (lane == 0) s_auxf[wid] = esum;
    __syncthreads();
    float tot = 0.f;
    #pragma unroll
    for (int w = 0; w < 8; w++) tot += s_auxf[w];
    float inv = 1.f / tot;
    // compaction of selected (index, weight), ordered by key index
    unsigned bals[10];
    #pragma unroll
    for (int i = 0; i < 10; i++) {
        bals[i] = __ballot_sync(0xffffffffu, sel[i]);
        if (lane == 0) s_seg[i*8 + wid] = __popc(bals[i]);
    }
    __syncthreads();
    if (tid < 80) { int p = 0; for (int q = 0; q < tid; q++) p += s_seg[q]; s_pref[tid] = p; }
    __syncthreads();
    #pragma unroll
    for (int i = 0; i < 10; i++) {
        if (sel[i]) {
            int pos = s_pref[i*8 + wid] + __popc(bals[i] & ltm);
            s_idx[pos] = i*256 + tid;
            s_wt[pos] = ev[i] * inv;
        }
    }
    __syncthreads();
    int d = tid & 63, grp = tid >> 6;
    const float* vb = g_vf + (size_t)bh*LFULL*HD;
    float acc = 0.f;
    for (int e2 = grp; e2 < KSEL_S; e2 += 4)
        acc += s_wt[e2] * vb[(size_t)s_idx[e2]*HD + d];
    s_part[grp][d] = acc;
    __syncthreads();
    if (tid < HD) {
        float o4 = s_part[0][tid] + s_part[1][tid] + s_part[2][tid] + s_part[3][tid];
        g_xo[((size_t)b*NTOK + NM + qs)*DIMC + h*HD + tid] = o4;
    }
}

// ---------------- launch ----------------
extern "C" void kernel_launch(void* const* d_in, const int* in_sizes, int n_in,
                              void* d_out, int out_size) {
    const float* x        = (const float*)d_in[0];
    const float* id_total = (const float*)d_in[1];
    const float* mem_k    = (const float*)d_in[2];
    const float* mem_v    = (const float*)d_in[3];
    const float* W_qkv    = (const float*)d_in[4];
    const float* b_qkv    = (const float*)d_in[5];
    const float* qkv_A    = (const float*)d_in[6];
    const float* qkv_B    = (const float*)d_in[7];
    const float* W_proj   = (const float*)d_in[8];
    const float* b_proj   = (const float*)d_in[9];
    const float* route_W  = (const float*)d_in[10];
    const float* proj_A   = (const float*)d_in[11];
    const float* proj_B   = (const float*)d_in[12];
    const float* W_idk    = (const float*)d_in[13];
    const float* b_idk    = (const float*)d_in[14];
    const float* idk_A    = (const float*)d_in[15];
    const float* idk_B    = (const float*)d_in[16];
    const float* W_idv    = (const float*)d_in[17];
    const float* b_idv    = (const float*)d_in[18];
    const float* idv_A    = (const float*)d_in[19];
    const float* idv_B    = (const float*)d_in[20];
    (void)in_sizes; (void)n_in; (void)out_size;

    float* out  = (float*)d_out;
    float* kmid = out + (size_t)Bsz*NTOK*DIMC;
    float* vmid = kmid + (size_t)BH*NM*HD;

    low_qkv_kernel<<<Bsz*NTOK, 256>>>(x, qkv_A);
    id_lows_kernel<<<Bsz*NM, 256>>>(id_total, idk_A, idv_A);
    gemm_qkv_kernel<<<dim3(36, 80), 256>>>(x, W_qkv, b_qkv, qkv_B);
    gemm_idv_kernel<<<dim3(12, 16), 256>>>(id_total, W_idv, b_idv, idv_B);
    idk_kernel<<<Bsz*NM, 256>>>(id_total, W_idk, b_idk, idk_B);
    build_kv_kernel<<<(BH*LFULL*HD)/256, 256>>>(mem_k, mem_v, kmid, vmid);
    score_gemm_m_kernel<<<dim3(4, 4, BH), 256>>>(kmid);
    topk_m_kernel<<<BH*NM, 256>>>(vmid);
    for (int c = 0; c < BH/CH; c++) {
        score_gemm_s_kernel<<<dim3(40, 16, CH), 256>>>(c*CH);
        topk_s_kernel<<<CH*NS, 256>>>(c*CH);
    }
    coef_kernel<<<Bsz*NTOK, 256>>>(route_W, proj_A);
    gemm_out_kernel<<<dim3(12, 80), 256>>>(W_proj, b_proj, proj_B, out);
}